// round 1
// baseline (speedup 1.0000x reference)
#include <cuda_runtime.h>

// Problem constants (fixed by reference)
#define NN    50000
#define NE    800000
#define NET   (NN + NE)   // edges incl. self loops = 850000
#define FDIM  128

// ---------------- scratch (device globals; no runtime allocation) ----------
__device__ float  g_bufA[NN * FDIM];   // h (x@W) per layer
__device__ float  g_bufB[NN * FDIM];   // feat (aggregated + bias + relu)
__device__ float4 g_AS[NN];            // alpha_src per node (4 heads)
__device__ float4 g_AD[NN];            // alpha_dst per node (4 heads)
__device__ int    g_cnt[NN];
__device__ int    g_rowptr[NN + 1];
__device__ int    g_woff[NN];
__device__ int    g_csrc[NET];
__device__ float  g_weff[FDIM];
__device__ float  g_beff;

// ---------------- CSR build ----------------
__global__ void zero_cnt_kernel() {
    int i = blockIdx.x * blockDim.x + threadIdx.x;
    if (i < NN) g_cnt[i] = 0;
}

__global__ void count_kernel(const int* __restrict__ edst) {
    int et = blockIdx.x * blockDim.x + threadIdx.x;
    if (et >= NET) return;
    int d = (et < NE) ? __ldg(&edst[et]) : (et - NE);
    atomicAdd(&g_cnt[d], 1);
}

__global__ __launch_bounds__(1024) void scan_kernel() {
    __shared__ int wsum[32];
    __shared__ int stotal;
    int tid = threadIdx.x, lane = tid & 31, wid = tid >> 5;
    int carry = 0;
    if (tid == 0) g_rowptr[0] = 0;
    for (int base = 0; base < NN; base += 1024) {
        int i = base + tid;
        int v = (i < NN) ? g_cnt[i] : 0;
        int x = v;
        #pragma unroll
        for (int o = 1; o < 32; o <<= 1) {
            int t = __shfl_up_sync(0xffffffffu, x, o);
            if (lane >= o) x += t;
        }
        if (lane == 31) wsum[wid] = x;
        __syncthreads();
        if (wid == 0) {
            int y = wsum[lane];
            #pragma unroll
            for (int o = 1; o < 32; o <<= 1) {
                int t = __shfl_up_sync(0xffffffffu, y, o);
                if (lane >= o) y += t;
            }
            wsum[lane] = y;
            if (lane == 31) stotal = y;
        }
        __syncthreads();
        int off = (wid > 0) ? wsum[wid - 1] : 0;
        int incl = carry + off + x;
        if (i < NN) {
            g_rowptr[i + 1] = incl;
            g_woff[i] = incl - v;  // exclusive offset (write cursor)
        }
        carry += stotal;
        __syncthreads();
    }
}

__global__ void scatter_kernel(const int* __restrict__ esrc,
                               const int* __restrict__ edst) {
    int et = blockIdx.x * blockDim.x + threadIdx.x;
    if (et >= NET) return;
    int s, d;
    if (et < NE) { s = __ldg(&esrc[et]); d = __ldg(&edst[et]); }
    else         { s = d = et - NE; }
    int pos = atomicAdd(&g_woff[d], 1);
    g_csrc[pos] = s;
}

// ---------------- GEMM: C[M,128] = A[M,128] @ W[128,128] ----------------
// BM=64 rows/block, full K=128, 256 threads, 4x8 register tile per thread.
__global__ __launch_bounds__(256) void gemm128_kernel(
    const float* __restrict__ A, const float* __restrict__ Wm,
    float* __restrict__ C, int M)
{
    extern __shared__ float smem[];
    float* xs = smem;                 // 64*128 floats
    float* ws = smem + 64 * FDIM;     // 128*128 floats

    int tid = threadIdx.x;
    int m0  = blockIdx.x * 64;

    // Stage W (16384 floats = 4096 float4)
    #pragma unroll
    for (int t = tid; t < 4096; t += 256)
        ((float4*)ws)[t] = ((const float4*)Wm)[t];
    // Stage x tile (8192 floats = 2048 float4), guard tail rows
    for (int t = tid; t < 2048; t += 256) {
        int row = t >> 5, c4 = t & 31;
        int gm = m0 + row;
        float4 v = (gm < M) ? ((const float4*)A)[gm * 32 + c4]
                            : make_float4(0.f, 0.f, 0.f, 0.f);
        ((float4*)xs)[row * 32 + c4] = v;
    }
    __syncthreads();

    int colg = tid & 15;     // 16 column groups: cols {colg*4..+3} and {64+colg*4..+3}
    int rowg = tid >> 4;     // 16 row groups: rows rowg*4..+3

    float4 acc0[4], acc1[4];
    #pragma unroll
    for (int i = 0; i < 4; i++) {
        acc0[i] = make_float4(0.f, 0.f, 0.f, 0.f);
        acc1[i] = make_float4(0.f, 0.f, 0.f, 0.f);
    }

    const float* xbase = xs + (rowg * 4) * FDIM;
    #pragma unroll 2
    for (int k = 0; k < 128; k += 4) {
        float xr[4][4];
        #pragma unroll
        for (int i = 0; i < 4; i++)
            *(float4*)xr[i] = *(const float4*)(xbase + i * FDIM + k);
        #pragma unroll
        for (int kk = 0; kk < 4; kk++) {
            float4 w0 = *(const float4*)(ws + (k + kk) * FDIM + colg * 4);
            float4 w1 = *(const float4*)(ws + (k + kk) * FDIM + 64 + colg * 4);
            #pragma unroll
            for (int i = 0; i < 4; i++) {
                float a = xr[i][kk];
                acc0[i].x = fmaf(a, w0.x, acc0[i].x);
                acc0[i].y = fmaf(a, w0.y, acc0[i].y);
                acc0[i].z = fmaf(a, w0.z, acc0[i].z);
                acc0[i].w = fmaf(a, w0.w, acc0[i].w);
                acc1[i].x = fmaf(a, w1.x, acc1[i].x);
                acc1[i].y = fmaf(a, w1.y, acc1[i].y);
                acc1[i].z = fmaf(a, w1.z, acc1[i].z);
                acc1[i].w = fmaf(a, w1.w, acc1[i].w);
            }
        }
    }

    #pragma unroll
    for (int i = 0; i < 4; i++) {
        int gm = m0 + rowg * 4 + i;
        if (gm < M) {
            ((float4*)C)[gm * 32 + colg]      = acc0[i];
            ((float4*)C)[gm * 32 + 16 + colg] = acc1[i];
        }
    }
}

// ---------------- alphas: per-node per-head dot(h, a_src/a_dst) ----------
__global__ __launch_bounds__(256) void alphas_kernel(
    const float* __restrict__ h,
    const float* __restrict__ a_src, const float* __restrict__ a_dst)
{
    int gw = (blockIdx.x * blockDim.x + threadIdx.x) >> 5;
    if (gw >= NN) return;
    int lane = threadIdx.x & 31;
    int head = lane >> 3, part = lane & 7;

    float4 hv = *(const float4*)(h + gw * FDIM + lane * 4);
    float4 s4 = *(const float4*)(a_src + head * 32 + part * 4);
    float4 d4 = *(const float4*)(a_dst + head * 32 + part * 4);
    float ps = hv.x * s4.x + hv.y * s4.y + hv.z * s4.z + hv.w * s4.w;
    float pd = hv.x * d4.x + hv.y * d4.y + hv.z * d4.z + hv.w * d4.w;
    #pragma unroll
    for (int o = 4; o >= 1; o >>= 1) {
        ps += __shfl_xor_sync(0xffffffffu, ps, o);
        pd += __shfl_xor_sync(0xffffffffu, pd, o);
    }
    if (part == 0) {
        ((float*)g_AS)[gw * 4 + head] = ps;
        ((float*)g_AD)[gw * 4 + head] = pd;
    }
}

// ---------------- aggregation: one warp per destination node -------------
__device__ __forceinline__ float leaky(float e) { return e > 0.f ? e : 0.2f * e; }
__device__ __forceinline__ float sel4(float4 v, int head) {
    return (head < 2) ? (head == 0 ? v.x : v.y) : (head == 2 ? v.z : v.w);
}

__global__ __launch_bounds__(256) void agg_kernel(
    const float* __restrict__ h, const float* __restrict__ bias,
    float* __restrict__ feat)
{
    int gw = (blockIdx.x * blockDim.x + threadIdx.x) >> 5;
    if (gw >= NN) return;
    int lane = threadIdx.x & 31;
    int n = gw;
    int beg = __ldg(&g_rowptr[n]);
    int end = __ldg(&g_rowptr[n + 1]);
    float4 ad = __ldg(&g_AD[n]);

    const float NINF = -1e30f;
    float4 mx = make_float4(NINF, NINF, NINF, NINF);
    for (int j = beg + lane; j < end; j += 32) {
        int s = __ldg(&g_csrc[j]);
        float4 as = __ldg(&g_AS[s]);
        mx.x = fmaxf(mx.x, leaky(as.x + ad.x));
        mx.y = fmaxf(mx.y, leaky(as.y + ad.y));
        mx.z = fmaxf(mx.z, leaky(as.z + ad.z));
        mx.w = fmaxf(mx.w, leaky(as.w + ad.w));
    }
    #pragma unroll
    for (int o = 16; o >= 1; o >>= 1) {
        mx.x = fmaxf(mx.x, __shfl_xor_sync(0xffffffffu, mx.x, o));
        mx.y = fmaxf(mx.y, __shfl_xor_sync(0xffffffffu, mx.y, o));
        mx.z = fmaxf(mx.z, __shfl_xor_sync(0xffffffffu, mx.z, o));
        mx.w = fmaxf(mx.w, __shfl_xor_sync(0xffffffffu, mx.w, o));
    }

    float4 sm = make_float4(0.f, 0.f, 0.f, 0.f);
    for (int j = beg + lane; j < end; j += 32) {
        int s = __ldg(&g_csrc[j]);
        float4 as = __ldg(&g_AS[s]);
        sm.x += __expf(leaky(as.x + ad.x) - mx.x);
        sm.y += __expf(leaky(as.y + ad.y) - mx.y);
        sm.z += __expf(leaky(as.z + ad.z) - mx.z);
        sm.w += __expf(leaky(as.w + ad.w) - mx.w);
    }
    #pragma unroll
    for (int o = 16; o >= 1; o >>= 1) {
        sm.x += __shfl_xor_sync(0xffffffffu, sm.x, o);
        sm.y += __shfl_xor_sync(0xffffffffu, sm.y, o);
        sm.z += __shfl_xor_sync(0xffffffffu, sm.z, o);
        sm.w += __shfl_xor_sync(0xffffffffu, sm.w, o);
    }

    int head = lane >> 3;
    float mh  = sel4(mx, head);
    float ih  = __fdividef(1.f, sel4(sm, head) + 1e-16f);
    float adh = sel4(ad, head);

    float4 acc = make_float4(0.f, 0.f, 0.f, 0.f);
    int sNext = (beg < end) ? __ldg(&g_csrc[beg]) : 0;
    for (int j = beg; j < end; j++) {
        int s = sNext;
        if (j + 1 < end) sNext = __ldg(&g_csrc[j + 1]);
        float ash = __ldg(((const float*)&g_AS[s]) + head);
        float w = __expf(leaky(ash + adh) - mh) * ih;
        float4 hv = *(const float4*)(h + s * FDIM + lane * 4);
        acc.x = fmaf(hv.x, w, acc.x);
        acc.y = fmaf(hv.y, w, acc.y);
        acc.z = fmaf(hv.z, w, acc.z);
        acc.w = fmaf(hv.w, w, acc.w);
    }

    float4 b = *(const float4*)(bias + lane * 4);
    float4 o;
    o.x = fmaxf(acc.x + b.x, 0.f);
    o.y = fmaxf(acc.y + b.y, 0.f);
    o.z = fmaxf(acc.z + b.z, 0.f);
    o.w = fmaxf(acc.w + b.w, 0.f);
    *(float4*)(feat + n * FDIM + lane * 4) = o;
}

// ---------------- classifier folding: w_eff = Wc1 @ Wc2 ------------------
__global__ void weff_kernel(const float* __restrict__ Wc1,
                            const float* __restrict__ bc1,
                            const float* __restrict__ Wc2,
                            const float* __restrict__ bc2)
{
    int t = threadIdx.x;
    if (t < 128) {
        float s = 0.f;
        #pragma unroll
        for (int j = 0; j < 32; j++) s += Wc1[t * 32 + j] * Wc2[j];
        g_weff[t] = s;
    }
    if (t == 0) {
        float b = bc2[0];
        for (int j = 0; j < 32; j++) b += bc1[j] * Wc2[j];
        g_beff = b;
    }
}

__global__ __launch_bounds__(256) void final_kernel(
    const float* __restrict__ feat, float* __restrict__ out)
{
    int gw = (blockIdx.x * blockDim.x + threadIdx.x) >> 5;
    if (gw >= NN) return;
    int lane = threadIdx.x & 31;
    float4 f = *(const float4*)(feat + gw * FDIM + lane * 4);
    float4 w = *(const float4*)(g_weff + lane * 4);
    float p = f.x * w.x + f.y * w.y + f.z * w.z + f.w * w.w;
    #pragma unroll
    for (int o = 16; o >= 1; o >>= 1)
        p += __shfl_xor_sync(0xffffffffu, p, o);
    if (lane == 0) {
        float z = p + g_beff;
        out[gw] = __fdividef(1.f, 1.f + __expf(-z));
    }
}

// ---------------- host launcher ----------------
extern "C" void kernel_launch(void* const* d_in, const int* in_sizes, int n_in,
                              void* d_out, int out_size)
{
    const float* x    = (const float*)d_in[0];
    const int*   ei   = (const int*)  d_in[1];
    const int*   esrc = ei;
    const int*   edst = ei + NE;
    const float* W1   = (const float*)d_in[2];
    const float* as1  = (const float*)d_in[3];
    const float* ad1  = (const float*)d_in[4];
    const float* b1   = (const float*)d_in[5];
    const float* W2   = (const float*)d_in[6];
    const float* as2  = (const float*)d_in[7];
    const float* ad2  = (const float*)d_in[8];
    const float* b2   = (const float*)d_in[9];
    const float* Wc1  = (const float*)d_in[10];
    const float* bc1  = (const float*)d_in[11];
    const float* Wc2  = (const float*)d_in[12];
    const float* bc2  = (const float*)d_in[13];
    float* out = (float*)d_out;

    float *bufA, *bufB;
    cudaGetSymbolAddress((void**)&bufA, g_bufA);
    cudaGetSymbolAddress((void**)&bufB, g_bufB);

    const size_t SMEM = (size_t)(64 * FDIM + FDIM * FDIM) * sizeof(float); // 96 KB
    cudaFuncSetAttribute(gemm128_kernel,
                         cudaFuncAttributeMaxDynamicSharedMemorySize, (int)SMEM);

    const int warpGrid = (NN * 32 + 255) / 256;   // one warp per node
    const int gemmGrid = (NN + 63) / 64;

    // CSR build (edge-only; reused by both layers)
    zero_cnt_kernel<<<(NN + 255) / 256, 256>>>();
    count_kernel<<<(NET + 255) / 256, 256>>>(edst);
    scan_kernel<<<1, 1024>>>();
    scatter_kernel<<<(NET + 255) / 256, 256>>>(esrc, edst);

    // Layer 1
    gemm128_kernel<<<gemmGrid, 256, SMEM>>>(x, W1, bufA, NN);
    alphas_kernel<<<warpGrid, 256>>>(bufA, as1, ad1);
    agg_kernel<<<warpGrid, 256>>>(bufA, b1, bufB);

    // Layer 2
    gemm128_kernel<<<gemmGrid, 256, SMEM>>>(bufB, W2, bufA, NN);
    alphas_kernel<<<warpGrid, 256>>>(bufA, as2, ad2);
    agg_kernel<<<warpGrid, 256>>>(bufA, b2, bufB);

    // Folded classifier + sigmoid
    weff_kernel<<<1, 128>>>(Wc1, bc1, Wc2, bc2);
    final_kernel<<<warpGrid, 256>>>(bufB, out);
}

// round 2
// speedup vs baseline: 1.0577x; 1.0577x over previous
#include <cuda_runtime.h>

// Problem constants (fixed by reference)
#define NN    50000
#define NE    800000
#define NET   (NN + NE)   // edges incl. self loops = 850000
#define FDIM  128

typedef unsigned long long ull;

// ---------------- scratch (device globals; no runtime allocation) ----------
__device__ float  g_bufA[NN * FDIM];   // h (x@W) per layer
__device__ float  g_bufB[NN * FDIM];   // feat (aggregated + bias + relu)
__device__ float4 g_AS[NN];            // alpha_src per node (4 heads)
__device__ float4 g_AD[NN];            // alpha_dst per node (4 heads)
__device__ int    g_cnt[NN];
__device__ int    g_rowptr[NN + 1];
__device__ int    g_woff[NN];
__device__ int    g_csrc[NET];
__device__ float  g_weff[FDIM];
__device__ float  g_beff;

// ---------------- packed f32x2 helpers ----------------
__device__ __forceinline__ ull pk2(float v) {
    ull r; asm("mov.b64 %0, {%1, %1};" : "=l"(r) : "f"(v)); return r;
}
__device__ __forceinline__ void ffma2(ull& d, ull a, ull b) {
    asm("fma.rn.f32x2 %0, %1, %2, %0;" : "+l"(d) : "l"(a), "l"(b));
}
__device__ __forceinline__ float2 up2(ull r) {
    float2 f; asm("mov.b64 {%0, %1}, %2;" : "=f"(f.x), "=f"(f.y) : "l"(r)); return f;
}

// ---------------- CSR build ----------------
__global__ void init_cnt_kernel() {
    int i = blockIdx.x * blockDim.x + threadIdx.x;
    if (i < NN) g_cnt[i] = 1;   // pre-count the self loop
}

__global__ void count4_kernel(const int* __restrict__ edst) {
    int t = blockIdx.x * blockDim.x + threadIdx.x;
    if (t >= NE / 4) return;
    int4 d = ((const int4*)edst)[t];
    atomicAdd(&g_cnt[d.x], 1);
    atomicAdd(&g_cnt[d.y], 1);
    atomicAdd(&g_cnt[d.z], 1);
    atomicAdd(&g_cnt[d.w], 1);
}

__global__ __launch_bounds__(1024) void scan_kernel() {
    __shared__ int wsum[32];
    __shared__ int stotal;
    int tid = threadIdx.x, lane = tid & 31, wid = tid >> 5;
    int carry = 0;
    if (tid == 0) g_rowptr[0] = 0;
    for (int base = 0; base < NN; base += 1024) {
        int i = base + tid;
        int v = (i < NN) ? g_cnt[i] : 0;
        int x = v;
        #pragma unroll
        for (int o = 1; o < 32; o <<= 1) {
            int t = __shfl_up_sync(0xffffffffu, x, o);
            if (lane >= o) x += t;
        }
        if (lane == 31) wsum[wid] = x;
        __syncthreads();
        if (wid == 0) {
            int y = wsum[lane];
            #pragma unroll
            for (int o = 1; o < 32; o <<= 1) {
                int t = __shfl_up_sync(0xffffffffu, y, o);
                if (lane >= o) y += t;
            }
            wsum[lane] = y;
            if (lane == 31) stotal = y;
        }
        __syncthreads();
        int off = (wid > 0) ? wsum[wid - 1] : 0;
        int incl = carry + off + x;
        if (i < NN) {
            g_rowptr[i + 1] = incl;
            g_woff[i] = incl - v;  // exclusive offset (write cursor)
        }
        carry += stotal;
        __syncthreads();
    }
}

__global__ void scatter4_kernel(const int* __restrict__ esrc,
                                const int* __restrict__ edst) {
    int t = blockIdx.x * blockDim.x + threadIdx.x;
    if (t >= NE / 4) return;
    int4 s = ((const int4*)esrc)[t];
    int4 d = ((const int4*)edst)[t];
    int p0 = atomicAdd(&g_woff[d.x], 1);
    int p1 = atomicAdd(&g_woff[d.y], 1);
    int p2 = atomicAdd(&g_woff[d.z], 1);
    int p3 = atomicAdd(&g_woff[d.w], 1);
    g_csrc[p0] = s.x;
    g_csrc[p1] = s.y;
    g_csrc[p2] = s.z;
    g_csrc[p3] = s.w;
}

__global__ void scatter_self_kernel() {
    int i = blockIdx.x * blockDim.x + threadIdx.x;
    if (i >= NN) return;
    int pos = atomicAdd(&g_woff[i], 1);
    g_csrc[pos] = i;
}

// ---------------- GEMM: C[M,128] = A[M,128] @ W[128,128] ----------------
// BM=64 rows/block, full K=128, 256 threads, 4x8 register tile per thread.
// Inner product uses packed fma.rn.f32x2 (FFMA2): 2x fp32 flops per issue slot.
__global__ __launch_bounds__(256) void gemm128_kernel(
    const float* __restrict__ A, const float* __restrict__ Wm,
    float* __restrict__ C, int M)
{
    extern __shared__ float smem[];
    float* xs = smem;                 // 64*128 floats
    float* ws = smem + 64 * FDIM;     // 128*128 floats

    int tid = threadIdx.x;
    int m0  = blockIdx.x * 64;

    // Stage W (16384 floats = 4096 float4)
    #pragma unroll
    for (int t = tid; t < 4096; t += 256)
        ((float4*)ws)[t] = ((const float4*)Wm)[t];
    // Stage x tile (8192 floats = 2048 float4), guard tail rows
    for (int t = tid; t < 2048; t += 256) {
        int row = t >> 5, c4 = t & 31;
        int gm = m0 + row;
        float4 v = (gm < M) ? ((const float4*)A)[gm * 32 + c4]
                            : make_float4(0.f, 0.f, 0.f, 0.f);
        ((float4*)xs)[row * 32 + c4] = v;
    }
    __syncthreads();

    int colg = tid & 15;     // 16 column groups: cols {colg*4..+3} and {64+colg*4..+3}
    int rowg = tid >> 4;     // 16 row groups: rows rowg*4..+3

    // acc[i][p]: row i, packed col pairs: p0={c,c+1} p1={c+2,c+3} of block0,
    //            p2,p3 same for block1 (cols +64)
    ull acc[4][4];
    #pragma unroll
    for (int i = 0; i < 4; i++)
        #pragma unroll
        for (int p = 0; p < 4; p++) acc[i][p] = 0ull;

    const float* xbase = xs + (rowg * 4) * FDIM;
    #pragma unroll 2
    for (int k = 0; k < 128; k += 4) {
        float xr[4][4];
        #pragma unroll
        for (int i = 0; i < 4; i++)
            *(float4*)xr[i] = *(const float4*)(xbase + i * FDIM + k);
        #pragma unroll
        for (int kk = 0; kk < 4; kk++) {
            ulonglong2 w0 = *(const ulonglong2*)(ws + (k + kk) * FDIM + colg * 4);
            ulonglong2 w1 = *(const ulonglong2*)(ws + (k + kk) * FDIM + 64 + colg * 4);
            #pragma unroll
            for (int i = 0; i < 4; i++) {
                ull ap = pk2(xr[i][kk]);
                ffma2(acc[i][0], ap, w0.x);
                ffma2(acc[i][1], ap, w0.y);
                ffma2(acc[i][2], ap, w1.x);
                ffma2(acc[i][3], ap, w1.y);
            }
        }
    }

    #pragma unroll
    for (int i = 0; i < 4; i++) {
        int gm = m0 + rowg * 4 + i;
        if (gm < M) {
            float2 a = up2(acc[i][0]), b = up2(acc[i][1]);
            float2 c = up2(acc[i][2]), d = up2(acc[i][3]);
            ((float4*)C)[gm * 32 + colg]      = make_float4(a.x, a.y, b.x, b.y);
            ((float4*)C)[gm * 32 + 16 + colg] = make_float4(c.x, c.y, d.x, d.y);
        }
    }
}

// ---------------- alphas: per-node per-head dot(h, a_src/a_dst) ----------
__global__ __launch_bounds__(256) void alphas_kernel(
    const float* __restrict__ h,
    const float* __restrict__ a_src, const float* __restrict__ a_dst)
{
    int gw = (blockIdx.x * blockDim.x + threadIdx.x) >> 5;
    if (gw >= NN) return;
    int lane = threadIdx.x & 31;
    int head = lane >> 3, part = lane & 7;

    float4 hv = *(const float4*)(h + gw * FDIM + lane * 4);
    float4 s4 = *(const float4*)(a_src + head * 32 + part * 4);
    float4 d4 = *(const float4*)(a_dst + head * 32 + part * 4);
    float ps = hv.x * s4.x + hv.y * s4.y + hv.z * s4.z + hv.w * s4.w;
    float pd = hv.x * d4.x + hv.y * d4.y + hv.z * d4.z + hv.w * d4.w;
    #pragma unroll
    for (int o = 4; o >= 1; o >>= 1) {
        ps += __shfl_xor_sync(0xffffffffu, ps, o);
        pd += __shfl_xor_sync(0xffffffffu, pd, o);
    }
    if (part == 0) {
        ((float*)g_AS)[gw * 4 + head] = ps;
        ((float*)g_AD)[gw * 4 + head] = pd;
    }
}

// ---------------- aggregation: one warp per destination node -------------
__device__ __forceinline__ float leaky(float e) { return e > 0.f ? e : 0.2f * e; }
__device__ __forceinline__ float sel4(float4 v, int head) {
    return (head < 2) ? (head == 0 ? v.x : v.y) : (head == 2 ? v.z : v.w);
}

__global__ __launch_bounds__(256) void agg_kernel(
    const float* __restrict__ h, const float* __restrict__ bias,
    float* __restrict__ feat)
{
    int gw = (blockIdx.x * blockDim.x + threadIdx.x) >> 5;
    if (gw >= NN) return;
    int lane = threadIdx.x & 31;
    int n = gw;
    int beg = __ldg(&g_rowptr[n]);
    int end = __ldg(&g_rowptr[n + 1]);
    float4 ad = __ldg(&g_AD[n]);

    const float NINF = -1e30f;
    float4 mx = make_float4(NINF, NINF, NINF, NINF);
    for (int j = beg + lane; j < end; j += 32) {
        int s = __ldg(&g_csrc[j]);
        float4 as = __ldg(&g_AS[s]);
        mx.x = fmaxf(mx.x, leaky(as.x + ad.x));
        mx.y = fmaxf(mx.y, leaky(as.y + ad.y));
        mx.z = fmaxf(mx.z, leaky(as.z + ad.z));
        mx.w = fmaxf(mx.w, leaky(as.w + ad.w));
    }
    #pragma unroll
    for (int o = 16; o >= 1; o >>= 1) {
        mx.x = fmaxf(mx.x, __shfl_xor_sync(0xffffffffu, mx.x, o));
        mx.y = fmaxf(mx.y, __shfl_xor_sync(0xffffffffu, mx.y, o));
        mx.z = fmaxf(mx.z, __shfl_xor_sync(0xffffffffu, mx.z, o));
        mx.w = fmaxf(mx.w, __shfl_xor_sync(0xffffffffu, mx.w, o));
    }

    float4 sm = make_float4(0.f, 0.f, 0.f, 0.f);
    for (int j = beg + lane; j < end; j += 32) {
        int s = __ldg(&g_csrc[j]);
        float4 as = __ldg(&g_AS[s]);
        sm.x += __expf(leaky(as.x + ad.x) - mx.x);
        sm.y += __expf(leaky(as.y + ad.y) - mx.y);
        sm.z += __expf(leaky(as.z + ad.z) - mx.z);
        sm.w += __expf(leaky(as.w + ad.w) - mx.w);
    }
    #pragma unroll
    for (int o = 16; o >= 1; o >>= 1) {
        sm.x += __shfl_xor_sync(0xffffffffu, sm.x, o);
        sm.y += __shfl_xor_sync(0xffffffffu, sm.y, o);
        sm.z += __shfl_xor_sync(0xffffffffu, sm.z, o);
        sm.w += __shfl_xor_sync(0xffffffffu, sm.w, o);
    }

    int head = lane >> 3;
    float mh  = sel4(mx, head);
    float ih  = __fdividef(1.f, sel4(sm, head) + 1e-16f);
    float adh = sel4(ad, head);

    float4 acc = make_float4(0.f, 0.f, 0.f, 0.f);
    int j = beg;
    // unrolled x4 for MLP on the h-row gathers (the L2-bound part)
    for (; j + 4 <= end; j += 4) {
        int s0 = __ldg(&g_csrc[j]);
        int s1 = __ldg(&g_csrc[j + 1]);
        int s2 = __ldg(&g_csrc[j + 2]);
        int s3 = __ldg(&g_csrc[j + 3]);
        float a0 = __ldg(((const float*)(g_AS + s0)) + head);
        float a1 = __ldg(((const float*)(g_AS + s1)) + head);
        float a2 = __ldg(((const float*)(g_AS + s2)) + head);
        float a3 = __ldg(((const float*)(g_AS + s3)) + head);
        float4 h0 = __ldg((const float4*)(h + s0 * FDIM) + lane);
        float4 h1 = __ldg((const float4*)(h + s1 * FDIM) + lane);
        float4 h2 = __ldg((const float4*)(h + s2 * FDIM) + lane);
        float4 h3 = __ldg((const float4*)(h + s3 * FDIM) + lane);
        float w0 = __expf(leaky(a0 + adh) - mh) * ih;
        float w1 = __expf(leaky(a1 + adh) - mh) * ih;
        float w2 = __expf(leaky(a2 + adh) - mh) * ih;
        float w3 = __expf(leaky(a3 + adh) - mh) * ih;
        acc.x = fmaf(h3.x, w3, fmaf(h2.x, w2, fmaf(h1.x, w1, fmaf(h0.x, w0, acc.x))));
        acc.y = fmaf(h3.y, w3, fmaf(h2.y, w2, fmaf(h1.y, w1, fmaf(h0.y, w0, acc.y))));
        acc.z = fmaf(h3.z, w3, fmaf(h2.z, w2, fmaf(h1.z, w1, fmaf(h0.z, w0, acc.z))));
        acc.w = fmaf(h3.w, w3, fmaf(h2.w, w2, fmaf(h1.w, w1, fmaf(h0.w, w0, acc.w))));
    }
    for (; j < end; j++) {
        int s = __ldg(&g_csrc[j]);
        float ash = __ldg(((const float*)(g_AS + s)) + head);
        float w = __expf(leaky(ash + adh) - mh) * ih;
        float4 hv = __ldg((const float4*)(h + s * FDIM) + lane);
        acc.x = fmaf(hv.x, w, acc.x);
        acc.y = fmaf(hv.y, w, acc.y);
        acc.z = fmaf(hv.z, w, acc.z);
        acc.w = fmaf(hv.w, w, acc.w);
    }

    float4 b = *(const float4*)(bias + lane * 4);
    float4 o;
    o.x = fmaxf(acc.x + b.x, 0.f);
    o.y = fmaxf(acc.y + b.y, 0.f);
    o.z = fmaxf(acc.z + b.z, 0.f);
    o.w = fmaxf(acc.w + b.w, 0.f);
    *(float4*)(feat + n * FDIM + lane * 4) = o;
}

// ---------------- classifier folding: w_eff = Wc1 @ Wc2 ------------------
__global__ void weff_kernel(const float* __restrict__ Wc1,
                            const float* __restrict__ bc1,
                            const float* __restrict__ Wc2,
                            const float* __restrict__ bc2)
{
    int t = threadIdx.x;
    if (t < 128) {
        float s = 0.f;
        #pragma unroll
        for (int j = 0; j < 32; j++) s += Wc1[t * 32 + j] * Wc2[j];
        g_weff[t] = s;
    }
    if (t == 0) {
        float b = bc2[0];
        for (int j = 0; j < 32; j++) b += bc1[j] * Wc2[j];
        g_beff = b;
    }
}

__global__ __launch_bounds__(256) void final_kernel(
    const float* __restrict__ feat, float* __restrict__ out)
{
    int gw = (blockIdx.x * blockDim.x + threadIdx.x) >> 5;
    if (gw >= NN) return;
    int lane = threadIdx.x & 31;
    float4 f = *(const float4*)(feat + gw * FDIM + lane * 4);
    float4 w = *(const float4*)(g_weff + lane * 4);
    float p = f.x * w.x + f.y * w.y + f.z * w.z + f.w * w.w;
    #pragma unroll
    for (int o = 16; o >= 1; o >>= 1)
        p += __shfl_xor_sync(0xffffffffu, p, o);
    if (lane == 0) {
        float z = p + g_beff;
        out[gw] = __fdividef(1.f, 1.f + __expf(-z));
    }
}

// ---------------- host launcher ----------------
extern "C" void kernel_launch(void* const* d_in, const int* in_sizes, int n_in,
                              void* d_out, int out_size)
{
    const float* x    = (const float*)d_in[0];
    const int*   ei   = (const int*)  d_in[1];
    const int*   esrc = ei;
    const int*   edst = ei + NE;
    const float* W1   = (const float*)d_in[2];
    const float* as1  = (const float*)d_in[3];
    const float* ad1  = (const float*)d_in[4];
    const float* b1   = (const float*)d_in[5];
    const float* W2   = (const float*)d_in[6];
    const float* as2  = (const float*)d_in[7];
    const float* ad2  = (const float*)d_in[8];
    const float* b2   = (const float*)d_in[9];
    const float* Wc1  = (const float*)d_in[10];
    const float* bc1  = (const float*)d_in[11];
    const float* Wc2  = (const float*)d_in[12];
    const float* bc2  = (const float*)d_in[13];
    float* out = (float*)d_out;

    float *bufA, *bufB;
    cudaGetSymbolAddress((void**)&bufA, g_bufA);
    cudaGetSymbolAddress((void**)&bufB, g_bufB);

    const size_t SMEM = (size_t)(64 * FDIM + FDIM * FDIM) * sizeof(float); // 96 KB
    cudaFuncSetAttribute(gemm128_kernel,
                         cudaFuncAttributeMaxDynamicSharedMemorySize, (int)SMEM);

    const int warpGrid = (NN * 32 + 255) / 256;   // one warp per node
    const int gemmGrid = (NN + 63) / 64;
    const int e4Grid   = (NE / 4 + 255) / 256;

    // CSR build (edge-only; reused by both layers)
    init_cnt_kernel<<<(NN + 255) / 256, 256>>>();
    count4_kernel<<<e4Grid, 256>>>(edst);
    scan_kernel<<<1, 1024>>>();
    scatter4_kernel<<<e4Grid, 256>>>(esrc, edst);
    scatter_self_kernel<<<(NN + 255) / 256, 256>>>();

    // Layer 1
    gemm128_kernel<<<gemmGrid, 256, SMEM>>>(x, W1, bufA, NN);
    alphas_kernel<<<warpGrid, 256>>>(bufA, as1, ad1);
    agg_kernel<<<warpGrid, 256>>>(bufA, b1, bufB);

    // Layer 2
    gemm128_kernel<<<gemmGrid, 256, SMEM>>>(bufB, W2, bufA, NN);
    alphas_kernel<<<warpGrid, 256>>>(bufA, as2, ad2);
    agg_kernel<<<warpGrid, 256>>>(bufA, b2, bufB);

    // Folded classifier + sigmoid
    weff_kernel<<<1, 128>>>(Wc1, bc1, Wc2, bc2);
    final_kernel<<<warpGrid, 256>>>(bufB, out);
}

// round 3
// speedup vs baseline: 1.4304x; 1.3524x over previous
#include <cuda_runtime.h>

// Problem constants (fixed by reference)
#define NN    50000
#define NE    800000
#define NET   (NN + NE)   // edges incl. self loops = 850000
#define FDIM  128
#define SCANB 1024
#define NSCAN ((NN + SCANB - 1) / SCANB)   // 49

typedef unsigned long long ull;

// ---------------- scratch (device globals; no runtime allocation) ----------
__device__ float  g_bufA[NN * FDIM];   // h (x@W) per layer
__device__ float  g_bufB[NN * FDIM];   // feat (aggregated + bias + relu)
__device__ float4 g_AS[NN];            // alpha_src per node (4 heads)
__device__ float4 g_AD[NN];            // alpha_dst per node (4 heads)
__device__ int    g_cnt[NN];
__device__ int    g_rowptr[NN + 1];
__device__ int    g_woff[NN];
__device__ int    g_csrc[NET];
__device__ int    g_bsum[64];
__device__ int    g_boff[64];
__device__ float  g_weff[FDIM];
__device__ float  g_beff;

// ---------------- packed f32x2 helpers ----------------
__device__ __forceinline__ ull pk2(float v) {
    ull r; asm("mov.b64 %0, {%1, %1};" : "=l"(r) : "f"(v)); return r;
}
__device__ __forceinline__ void ffma2(ull& d, ull a, ull b) {
    asm("fma.rn.f32x2 %0, %1, %2, %0;" : "+l"(d) : "l"(a), "l"(b));
}
__device__ __forceinline__ float2 up2(ull r) {
    float2 f; asm("mov.b64 {%0, %1}, %2;" : "=f"(f.x), "=f"(f.y) : "l"(r)); return f;
}

// ---------------- CSR build ----------------
__global__ void init_cnt_kernel() {
    int i = blockIdx.x * blockDim.x + threadIdx.x;
    if (i < NN) g_cnt[i] = 1;   // pre-count the self loop
}

__global__ void count4_kernel(const int* __restrict__ edst) {
    int t = blockIdx.x * blockDim.x + threadIdx.x;
    if (t >= NE / 4) return;
    int4 d = ((const int4*)edst)[t];
    atomicAdd(&g_cnt[d.x], 1);
    atomicAdd(&g_cnt[d.y], 1);
    atomicAdd(&g_cnt[d.z], 1);
    atomicAdd(&g_cnt[d.w], 1);
}

// multi-block scan, stage 1: per-block inclusive scan + block sums
__global__ __launch_bounds__(SCANB) void scan1_kernel() {
    __shared__ int wsum[32];
    int tid = threadIdx.x, lane = tid & 31, wid = tid >> 5;
    int i = blockIdx.x * SCANB + tid;
    int v = (i < NN) ? g_cnt[i] : 0;
    int x = v;
    #pragma unroll
    for (int o = 1; o < 32; o <<= 1) {
        int t = __shfl_up_sync(0xffffffffu, x, o);
        if (lane >= o) x += t;
    }
    if (lane == 31) wsum[wid] = x;
    __syncthreads();
    if (wid == 0) {
        int y = wsum[lane];
        #pragma unroll
        for (int o = 1; o < 32; o <<= 1) {
            int t = __shfl_up_sync(0xffffffffu, y, o);
            if (lane >= o) y += t;
        }
        wsum[lane] = y;
    }
    __syncthreads();
    int incl = x + ((wid > 0) ? wsum[wid - 1] : 0);
    if (i < NN) g_rowptr[i + 1] = incl;       // local inclusive (fixed in stage 3)
    if (tid == SCANB - 1) g_bsum[blockIdx.x] = wsum[31];
}

// stage 2: scan the 49 block sums (one small block)
__global__ void scan2_kernel() {
    __shared__ int sm[64];
    int tid = threadIdx.x;
    int v = (tid < NSCAN) ? g_bsum[tid] : 0;
    sm[tid] = v;
    __syncthreads();
    #pragma unroll
    for (int o = 1; o < 64; o <<= 1) {
        int t = (tid >= o) ? sm[tid - o] : 0;
        __syncthreads();
        sm[tid] += t;
        __syncthreads();
    }
    if (tid < NSCAN) g_boff[tid] = sm[tid] - v;   // exclusive block offset
}

// stage 3: apply block offsets, produce rowptr + write cursors
__global__ void scan3_kernel() {
    int i = blockIdx.x * blockDim.x + threadIdx.x;
    if (i >= NN) return;
    int r = g_rowptr[i + 1] + g_boff[i >> 10];
    g_rowptr[i + 1] = r;
    g_woff[i] = r - g_cnt[i];
    if (i == 0) g_rowptr[0] = 0;
}

__global__ void scatter4_kernel(const int* __restrict__ esrc,
                                const int* __restrict__ edst) {
    int t = blockIdx.x * blockDim.x + threadIdx.x;
    if (t >= NE / 4) return;
    int4 s = ((const int4*)esrc)[t];
    int4 d = ((const int4*)edst)[t];
    int p0 = atomicAdd(&g_woff[d.x], 1);
    int p1 = atomicAdd(&g_woff[d.y], 1);
    int p2 = atomicAdd(&g_woff[d.z], 1);
    int p3 = atomicAdd(&g_woff[d.w], 1);
    g_csrc[p0] = s.x;
    g_csrc[p1] = s.y;
    g_csrc[p2] = s.z;
    g_csrc[p3] = s.w;
}

__global__ void scatter_self_kernel() {
    int i = blockIdx.x * blockDim.x + threadIdx.x;
    if (i >= NN) return;
    int pos = atomicAdd(&g_woff[i], 1);
    g_csrc[pos] = i;
}

// ---------------- GEMM: C[M,128] = A[M,128] @ W[128,128] ----------------
__global__ __launch_bounds__(256) void gemm128_kernel(
    const float* __restrict__ A, const float* __restrict__ Wm,
    float* __restrict__ C, int M)
{
    extern __shared__ float smem[];
    float* xs = smem;                 // 64*128 floats
    float* ws = smem + 64 * FDIM;     // 128*128 floats

    int tid = threadIdx.x;
    int m0  = blockIdx.x * 64;

    #pragma unroll
    for (int t = tid; t < 4096; t += 256)
        ((float4*)ws)[t] = ((const float4*)Wm)[t];
    for (int t = tid; t < 2048; t += 256) {
        int row = t >> 5, c4 = t & 31;
        int gm = m0 + row;
        float4 v = (gm < M) ? ((const float4*)A)[gm * 32 + c4]
                            : make_float4(0.f, 0.f, 0.f, 0.f);
        ((float4*)xs)[row * 32 + c4] = v;
    }
    __syncthreads();

    int colg = tid & 15;
    int rowg = tid >> 4;

    ull acc[4][4];
    #pragma unroll
    for (int i = 0; i < 4; i++)
        #pragma unroll
        for (int p = 0; p < 4; p++) acc[i][p] = 0ull;

    const float* xbase = xs + (rowg * 4) * FDIM;
    #pragma unroll 2
    for (int k = 0; k < 128; k += 4) {
        float xr[4][4];
        #pragma unroll
        for (int i = 0; i < 4; i++)
            *(float4*)xr[i] = *(const float4*)(xbase + i * FDIM + k);
        #pragma unroll
        for (int kk = 0; kk < 4; kk++) {
            ulonglong2 w0 = *(const ulonglong2*)(ws + (k + kk) * FDIM + colg * 4);
            ulonglong2 w1 = *(const ulonglong2*)(ws + (k + kk) * FDIM + 64 + colg * 4);
            #pragma unroll
            for (int i = 0; i < 4; i++) {
                ull ap = pk2(xr[i][kk]);
                ffma2(acc[i][0], ap, w0.x);
                ffma2(acc[i][1], ap, w0.y);
                ffma2(acc[i][2], ap, w1.x);
                ffma2(acc[i][3], ap, w1.y);
            }
        }
    }

    #pragma unroll
    for (int i = 0; i < 4; i++) {
        int gm = m0 + rowg * 4 + i;
        if (gm < M) {
            float2 a = up2(acc[i][0]), b = up2(acc[i][1]);
            float2 c = up2(acc[i][2]), d = up2(acc[i][3]);
            ((float4*)C)[gm * 32 + colg]      = make_float4(a.x, a.y, b.x, b.y);
            ((float4*)C)[gm * 32 + 16 + colg] = make_float4(c.x, c.y, d.x, d.y);
        }
    }
}

// ---------------- alphas: per-node per-head dot(h, a_src/a_dst) ----------
__global__ __launch_bounds__(256) void alphas_kernel(
    const float* __restrict__ h,
    const float* __restrict__ a_src, const float* __restrict__ a_dst)
{
    int gw = (blockIdx.x * blockDim.x + threadIdx.x) >> 5;
    if (gw >= NN) return;
    int lane = threadIdx.x & 31;
    int head = lane >> 3, part = lane & 7;

    float4 hv = *(const float4*)(h + gw * FDIM + lane * 4);
    float4 s4 = *(const float4*)(a_src + head * 32 + part * 4);
    float4 d4 = *(const float4*)(a_dst + head * 32 + part * 4);
    float ps = hv.x * s4.x + hv.y * s4.y + hv.z * s4.z + hv.w * s4.w;
    float pd = hv.x * d4.x + hv.y * d4.y + hv.z * d4.z + hv.w * d4.w;
    #pragma unroll
    for (int o = 4; o >= 1; o >>= 1) {
        ps += __shfl_xor_sync(0xffffffffu, ps, o);
        pd += __shfl_xor_sync(0xffffffffu, pd, o);
    }
    if (part == 0) {
        ((float*)g_AS)[gw * 4 + head] = ps;
        ((float*)g_AD)[gw * 4 + head] = pd;
    }
}

// ---------------- single-pass aggregation (no max pass; exact softmax) ----
// alpha_j = exp(e_j - m)/sum == exp(e_j)/sum(exp(e_j)); e = O(5) so fp32 safe.
__device__ __forceinline__ float leaky(float e) { return e > 0.f ? e : 0.2f * e; }

// body: accumulates acc (weighted h) and wsum for warp `gw`'s node
__device__ __forceinline__ void agg_body(
    const float* __restrict__ h, int gw, int lane, int head,
    float4& acc, float& wsum)
{
    int beg = __ldg(&g_rowptr[gw]);
    int end = __ldg(&g_rowptr[gw + 1]);
    float adh = __ldg(((const float*)(g_AD + gw)) + head);

    int j = beg;
    for (; j + 4 <= end; j += 4) {
        int s0 = __ldg(&g_csrc[j]);
        int s1 = __ldg(&g_csrc[j + 1]);
        int s2 = __ldg(&g_csrc[j + 2]);
        int s3 = __ldg(&g_csrc[j + 3]);
        float a0 = __ldg(((const float*)(g_AS + s0)) + head);
        float a1 = __ldg(((const float*)(g_AS + s1)) + head);
        float a2 = __ldg(((const float*)(g_AS + s2)) + head);
        float a3 = __ldg(((const float*)(g_AS + s3)) + head);
        float4 h0 = __ldg((const float4*)(h + s0 * FDIM) + lane);
        float4 h1 = __ldg((const float4*)(h + s1 * FDIM) + lane);
        float4 h2 = __ldg((const float4*)(h + s2 * FDIM) + lane);
        float4 h3 = __ldg((const float4*)(h + s3 * FDIM) + lane);
        float w0 = __expf(leaky(a0 + adh));
        float w1 = __expf(leaky(a1 + adh));
        float w2 = __expf(leaky(a2 + adh));
        float w3 = __expf(leaky(a3 + adh));
        wsum += (w0 + w1) + (w2 + w3);
        acc.x = fmaf(h3.x, w3, fmaf(h2.x, w2, fmaf(h1.x, w1, fmaf(h0.x, w0, acc.x))));
        acc.y = fmaf(h3.y, w3, fmaf(h2.y, w2, fmaf(h1.y, w1, fmaf(h0.y, w0, acc.y))));
        acc.z = fmaf(h3.z, w3, fmaf(h2.z, w2, fmaf(h1.z, w1, fmaf(h0.z, w0, acc.z))));
        acc.w = fmaf(h3.w, w3, fmaf(h2.w, w2, fmaf(h1.w, w1, fmaf(h0.w, w0, acc.w))));
    }
    for (; j < end; j++) {
        int s = __ldg(&g_csrc[j]);
        float a = __ldg(((const float*)(g_AS + s)) + head);
        float w = __expf(leaky(a + adh));
        float4 hv = __ldg((const float4*)(h + s * FDIM) + lane);
        wsum += w;
        acc.x = fmaf(hv.x, w, acc.x);
        acc.y = fmaf(hv.y, w, acc.y);
        acc.z = fmaf(hv.z, w, acc.z);
        acc.w = fmaf(hv.w, w, acc.w);
    }
}

// layer-1 variant: write feat = relu(acc/wsum + bias)
__global__ __launch_bounds__(256) void agg_fused_kernel(
    const float* __restrict__ h, const float* __restrict__ bias,
    float* __restrict__ feat)
{
    int gw = (blockIdx.x * blockDim.x + threadIdx.x) >> 5;
    if (gw >= NN) return;
    int lane = threadIdx.x & 31;
    int head = lane >> 3;

    float4 acc = make_float4(0.f, 0.f, 0.f, 0.f);
    float wsum = 0.f;
    agg_body(h, gw, lane, head, acc, wsum);

    float inv = __fdividef(1.f, wsum + 1e-16f);
    float4 b = *(const float4*)(bias + lane * 4);
    float4 o;
    o.x = fmaxf(fmaf(acc.x, inv, b.x), 0.f);
    o.y = fmaxf(fmaf(acc.y, inv, b.y), 0.f);
    o.z = fmaxf(fmaf(acc.z, inv, b.z), 0.f);
    o.w = fmaxf(fmaf(acc.w, inv, b.w), 0.f);
    *(float4*)(feat + gw * FDIM + lane * 4) = o;
}

// layer-2 variant: fuse classifier dot + sigmoid, write out[n] directly
__global__ __launch_bounds__(256) void agg_final_kernel(
    const float* __restrict__ h, const float* __restrict__ bias,
    float* __restrict__ out)
{
    int gw = (blockIdx.x * blockDim.x + threadIdx.x) >> 5;
    if (gw >= NN) return;
    int lane = threadIdx.x & 31;
    int head = lane >> 3;

    float4 acc = make_float4(0.f, 0.f, 0.f, 0.f);
    float wsum = 0.f;
    agg_body(h, gw, lane, head, acc, wsum);

    float inv = __fdividef(1.f, wsum + 1e-16f);
    float4 b = *(const float4*)(bias + lane * 4);
    float4 o;
    o.x = fmaxf(fmaf(acc.x, inv, b.x), 0.f);
    o.y = fmaxf(fmaf(acc.y, inv, b.y), 0.f);
    o.z = fmaxf(fmaf(acc.z, inv, b.z), 0.f);
    o.w = fmaxf(fmaf(acc.w, inv, b.w), 0.f);

    float4 w = *(const float4*)(g_weff + lane * 4);
    float p = o.x * w.x + o.y * w.y + o.z * w.z + o.w * w.w;
    #pragma unroll
    for (int of = 16; of >= 1; of >>= 1)
        p += __shfl_xor_sync(0xffffffffu, p, of);
    if (lane == 0) {
        float z = p + g_beff;
        out[gw] = __fdividef(1.f, 1.f + __expf(-z));
    }
}

// ---------------- classifier folding: w_eff = Wc1 @ Wc2 ------------------
__global__ void weff_kernel(const float* __restrict__ Wc1,
                            const float* __restrict__ bc1,
                            const float* __restrict__ Wc2,
                            const float* __restrict__ bc2)
{
    int t = threadIdx.x;
    if (t < 128) {
        float s = 0.f;
        #pragma unroll
        for (int j = 0; j < 32; j++) s += Wc1[t * 32 + j] * Wc2[j];
        g_weff[t] = s;
    }
    if (t == 0) {
        float b = bc2[0];
        for (int j = 0; j < 32; j++) b += bc1[j] * Wc2[j];
        g_beff = b;
    }
}

// ---------------- host launcher ----------------
extern "C" void kernel_launch(void* const* d_in, const int* in_sizes, int n_in,
                              void* d_out, int out_size)
{
    const float* x    = (const float*)d_in[0];
    const int*   ei   = (const int*)  d_in[1];
    const int*   esrc = ei;
    const int*   edst = ei + NE;
    const float* W1   = (const float*)d_in[2];
    const float* as1  = (const float*)d_in[3];
    const float* ad1  = (const float*)d_in[4];
    const float* b1   = (const float*)d_in[5];
    const float* W2   = (const float*)d_in[6];
    const float* as2  = (const float*)d_in[7];
    const float* ad2  = (const float*)d_in[8];
    const float* b2   = (const float*)d_in[9];
    const float* Wc1  = (const float*)d_in[10];
    const float* bc1  = (const float*)d_in[11];
    const float* Wc2  = (const float*)d_in[12];
    const float* bc2  = (const float*)d_in[13];
    float* out = (float*)d_out;

    float *bufA, *bufB;
    cudaGetSymbolAddress((void**)&bufA, g_bufA);
    cudaGetSymbolAddress((void**)&bufB, g_bufB);

    // one-time side stream + events (no device memory involved)
    static cudaStream_t s2 = nullptr;
    static cudaEvent_t evFork = nullptr, evJoin = nullptr;
    if (!s2) {
        cudaStreamCreateWithFlags(&s2, cudaStreamNonBlocking);
        cudaEventCreateWithFlags(&evFork, cudaEventDisableTiming);
        cudaEventCreateWithFlags(&evJoin, cudaEventDisableTiming);
    }

    const size_t SMEM = (size_t)(64 * FDIM + FDIM * FDIM) * sizeof(float); // 96 KB
    cudaFuncSetAttribute(gemm128_kernel,
                         cudaFuncAttributeMaxDynamicSharedMemorySize, (int)SMEM);

    const int warpGrid = (NN * 32 + 255) / 256;   // one warp per node
    const int gemmGrid = (NN + 63) / 64;
    const int e4Grid   = (NE / 4 + 255) / 256;
    const int nGrid    = (NN + 255) / 256;

    // Fork: CSR build + classifier fold on side stream, concurrent with GEMM1
    cudaEventRecord(evFork, 0);
    cudaStreamWaitEvent(s2, evFork, 0);

    init_cnt_kernel<<<nGrid, 256, 0, s2>>>();
    count4_kernel<<<e4Grid, 256, 0, s2>>>(edst);
    scan1_kernel<<<NSCAN, SCANB, 0, s2>>>();
    scan2_kernel<<<1, 64, 0, s2>>>();
    scan3_kernel<<<nGrid, 256, 0, s2>>>();
    scatter4_kernel<<<e4Grid, 256, 0, s2>>>(esrc, edst);
    scatter_self_kernel<<<nGrid, 256, 0, s2>>>();
    weff_kernel<<<1, 128, 0, s2>>>(Wc1, bc1, Wc2, bc2);
    cudaEventRecord(evJoin, s2);

    // Main stream: layer-1 dense part
    gemm128_kernel<<<gemmGrid, 256, SMEM>>>(x, W1, bufA, NN);
    alphas_kernel<<<warpGrid, 256>>>(bufA, as1, ad1);

    // Join before aggregation (needs CSR)
    cudaStreamWaitEvent(0, evJoin, 0);

    agg_fused_kernel<<<warpGrid, 256>>>(bufA, b1, bufB);

    // Layer 2
    gemm128_kernel<<<gemmGrid, 256, SMEM>>>(bufB, W2, bufA, NN);
    alphas_kernel<<<warpGrid, 256>>>(bufA, as2, ad2);
    agg_final_kernel<<<warpGrid, 256>>>(bufA, b2, out);
}

// round 4
// speedup vs baseline: 1.4794x; 1.0343x over previous
#include <cuda_runtime.h>
#include <cuda_fp16.h>

// Problem constants (fixed by reference)
#define NN    50000
#define NE    800000
#define NET   (NN + NE)   // edges incl. self loops = 850000
#define FDIM  128
#define SCANB 1024
#define NSCAN ((NN + SCANB - 1) / SCANB)   // 49

typedef unsigned long long ull;

// ---------------- scratch (device globals; no runtime allocation) ----------
__device__ __half g_h16[NN * FDIM];    // fp16 gather table (per layer, reused)
__device__ float  g_feat[NN * FDIM];   // layer-1 output (fp32, GEMM2 input)
__device__ float4 g_AS[NN];            // alpha_src per node (4 heads)
__device__ float4 g_AD[NN];            // alpha_dst per node (4 heads)
__device__ int    g_cnt[NN];
__device__ int    g_rowptr[NN + 1];
__device__ int    g_woff[NN];
__device__ int    g_csrc[NET];
__device__ int    g_bsum[64];
__device__ int    g_boff[64];
__device__ float  g_weff[FDIM];
__device__ float  g_beff;

// ---------------- packed f32x2 helpers ----------------
__device__ __forceinline__ ull pk2(float v) {
    ull r; asm("mov.b64 %0, {%1, %1};" : "=l"(r) : "f"(v)); return r;
}
__device__ __forceinline__ void ffma2(ull& d, ull a, ull b) {
    asm("fma.rn.f32x2 %0, %1, %2, %0;" : "+l"(d) : "l"(a), "l"(b));
}
__device__ __forceinline__ float2 up2(ull r) {
    float2 f; asm("mov.b64 {%0, %1}, %2;" : "=f"(f.x), "=f"(f.y) : "l"(r)); return f;
}

// ---------------- CSR build ----------------
__global__ void init_cnt_kernel() {
    int i = blockIdx.x * blockDim.x + threadIdx.x;
    if (i < NN) g_cnt[i] = 1;   // pre-count the self loop
}

__global__ void count4_kernel(const int* __restrict__ edst) {
    int t = blockIdx.x * blockDim.x + threadIdx.x;
    if (t >= NE / 4) return;
    int4 d = ((const int4*)edst)[t];
    atomicAdd(&g_cnt[d.x], 1);
    atomicAdd(&g_cnt[d.y], 1);
    atomicAdd(&g_cnt[d.z], 1);
    atomicAdd(&g_cnt[d.w], 1);
}

__global__ __launch_bounds__(SCANB) void scan1_kernel() {
    __shared__ int wsum[32];
    int tid = threadIdx.x, lane = tid & 31, wid = tid >> 5;
    int i = blockIdx.x * SCANB + tid;
    int v = (i < NN) ? g_cnt[i] : 0;
    int x = v;
    #pragma unroll
    for (int o = 1; o < 32; o <<= 1) {
        int t = __shfl_up_sync(0xffffffffu, x, o);
        if (lane >= o) x += t;
    }
    if (lane == 31) wsum[wid] = x;
    __syncthreads();
    if (wid == 0) {
        int y = wsum[lane];
        #pragma unroll
        for (int o = 1; o < 32; o <<= 1) {
            int t = __shfl_up_sync(0xffffffffu, y, o);
            if (lane >= o) y += t;
        }
        wsum[lane] = y;
    }
    __syncthreads();
    int incl = x + ((wid > 0) ? wsum[wid - 1] : 0);
    if (i < NN) g_rowptr[i + 1] = incl;
    if (tid == SCANB - 1) g_bsum[blockIdx.x] = wsum[31];
}

__global__ void scan2_kernel() {
    __shared__ int sm[64];
    int tid = threadIdx.x;
    int v = (tid < NSCAN) ? g_bsum[tid] : 0;
    sm[tid] = v;
    __syncthreads();
    #pragma unroll
    for (int o = 1; o < 64; o <<= 1) {
        int t = (tid >= o) ? sm[tid - o] : 0;
        __syncthreads();
        sm[tid] += t;
        __syncthreads();
    }
    if (tid < NSCAN) g_boff[tid] = sm[tid] - v;
}

__global__ void scan3_kernel() {
    int i = blockIdx.x * blockDim.x + threadIdx.x;
    if (i >= NN) return;
    int r = g_rowptr[i + 1] + g_boff[i >> 10];
    g_rowptr[i + 1] = r;
    g_woff[i] = r - g_cnt[i];
    if (i == 0) g_rowptr[0] = 0;
}

// 8 edges per thread for more outstanding atomics (latency-bound)
__global__ void scatter8_kernel(const int* __restrict__ esrc,
                                const int* __restrict__ edst) {
    int t = blockIdx.x * blockDim.x + threadIdx.x;
    if (t >= NE / 8) return;
    int4 s0 = ((const int4*)esrc)[2 * t];
    int4 s1 = ((const int4*)esrc)[2 * t + 1];
    int4 d0 = ((const int4*)edst)[2 * t];
    int4 d1 = ((const int4*)edst)[2 * t + 1];
    int p0 = atomicAdd(&g_woff[d0.x], 1);
    int p1 = atomicAdd(&g_woff[d0.y], 1);
    int p2 = atomicAdd(&g_woff[d0.z], 1);
    int p3 = atomicAdd(&g_woff[d0.w], 1);
    int p4 = atomicAdd(&g_woff[d1.x], 1);
    int p5 = atomicAdd(&g_woff[d1.y], 1);
    int p6 = atomicAdd(&g_woff[d1.z], 1);
    int p7 = atomicAdd(&g_woff[d1.w], 1);
    g_csrc[p0] = s0.x; g_csrc[p1] = s0.y; g_csrc[p2] = s0.z; g_csrc[p3] = s0.w;
    g_csrc[p4] = s1.x; g_csrc[p5] = s1.y; g_csrc[p6] = s1.z; g_csrc[p7] = s1.w;
}

__global__ void scatter_self_kernel() {
    int i = blockIdx.x * blockDim.x + threadIdx.x;
    if (i >= NN) return;
    int pos = atomicAdd(&g_woff[i], 1);
    g_csrc[pos] = i;
}

// ---- GEMM + fused alpha + fp16 h emit ------------------------------------
// C = A[M,128] @ W[128,128]; writes h16 (fp16) and AS/AD (fp32 exact alphas).
// Column index equals flat a_src/a_dst index (head*32+d == col).
__global__ __launch_bounds__(256) void gemm_fused_kernel(
    const float* __restrict__ A, const float* __restrict__ Wm,
    const float* __restrict__ a_src, const float* __restrict__ a_dst,
    __half* __restrict__ h16, int M)
{
    extern __shared__ float smem[];
    float* xs = smem;                 // 64*128
    float* ws = smem + 64 * FDIM;     // 128*128

    int tid = threadIdx.x;
    int m0  = blockIdx.x * 64;

    #pragma unroll
    for (int t = tid; t < 4096; t += 256)
        ((float4*)ws)[t] = ((const float4*)Wm)[t];
    for (int t = tid; t < 2048; t += 256) {
        int row = t >> 5, c4 = t & 31;
        int gm = m0 + row;
        float4 v = (gm < M) ? ((const float4*)A)[gm * 32 + c4]
                            : make_float4(0.f, 0.f, 0.f, 0.f);
        ((float4*)xs)[row * 32 + c4] = v;
    }
    __syncthreads();

    int colg = tid & 15;
    int rowg = tid >> 4;

    ull acc[4][4];
    #pragma unroll
    for (int i = 0; i < 4; i++)
        #pragma unroll
        for (int p = 0; p < 4; p++) acc[i][p] = 0ull;

    const float* xbase = xs + (rowg * 4) * FDIM;
    #pragma unroll 2
    for (int k = 0; k < 128; k += 4) {
        float xr[4][4];
        #pragma unroll
        for (int i = 0; i < 4; i++)
            *(float4*)xr[i] = *(const float4*)(xbase + i * FDIM + k);
        #pragma unroll
        for (int kk = 0; kk < 4; kk++) {
            ulonglong2 w0 = *(const ulonglong2*)(ws + (k + kk) * FDIM + colg * 4);
            ulonglong2 w1 = *(const ulonglong2*)(ws + (k + kk) * FDIM + 64 + colg * 4);
            #pragma unroll
            for (int i = 0; i < 4; i++) {
                ull ap = pk2(xr[i][kk]);
                ffma2(acc[i][0], ap, w0.x);
                ffma2(acc[i][1], ap, w0.y);
                ffma2(acc[i][2], ap, w1.x);
                ffma2(acc[i][3], ap, w1.y);
            }
        }
    }

    // attention vectors for this thread's 8 columns (flat index == col)
    float4 asl = __ldg((const float4*)a_src + colg);
    float4 ash = __ldg((const float4*)a_src + 16 + colg);
    float4 adl = __ldg((const float4*)a_dst + colg);
    float4 adh = __ldg((const float4*)a_dst + 16 + colg);

    #pragma unroll
    for (int i = 0; i < 4; i++) {
        int gm = m0 + rowg * 4 + i;
        if (gm >= M) continue;
        float2 a = up2(acc[i][0]), b = up2(acc[i][1]);
        float2 c = up2(acc[i][2]), d = up2(acc[i][3]);

        // fp16 h row (gather table)
        __half2 ph0 = __float22half2_rn(make_float2(a.x, a.y));
        __half2 ph1 = __float22half2_rn(make_float2(b.x, b.y));
        __half2 ph2 = __float22half2_rn(make_float2(c.x, c.y));
        __half2 ph3 = __float22half2_rn(make_float2(d.x, d.y));
        *(uint2*)(h16 + gm * FDIM + colg * 4) =
            make_uint2(*(unsigned*)&ph0, *(unsigned*)&ph1);
        *(uint2*)(h16 + gm * FDIM + 64 + colg * 4) =
            make_uint2(*(unsigned*)&ph2, *(unsigned*)&ph3);

        // alpha partials: low half -> head colg/8, high half -> head 2+colg/8
        float pls = a.x * asl.x + a.y * asl.y + b.x * asl.z + b.y * asl.w;
        float pld = a.x * adl.x + a.y * adl.y + b.x * adl.z + b.y * adl.w;
        float phs = c.x * ash.x + c.y * ash.y + d.x * ash.z + d.y * ash.w;
        float phd = c.x * adh.x + c.y * adh.y + d.x * adh.z + d.y * adh.w;
        #pragma unroll
        for (int o = 1; o < 8; o <<= 1) {
            pls += __shfl_xor_sync(0xffffffffu, pls, o);
            pld += __shfl_xor_sync(0xffffffffu, pld, o);
            phs += __shfl_xor_sync(0xffffffffu, phs, o);
            phd += __shfl_xor_sync(0xffffffffu, phd, o);
        }
        if ((colg & 7) == 0) {
            int g = colg >> 3;            // 0 or 1
            float* asp = (float*)(g_AS + gm);
            float* adp = (float*)(g_AD + gm);
            asp[g] = pls;  asp[2 + g] = phs;
            adp[g] = pld;  adp[2 + g] = phd;
        }
    }
}

// ---------------- single-pass aggregation over fp16 h ---------------------
__device__ __forceinline__ float leaky(float e) { return e > 0.f ? e : 0.2f * e; }

__device__ __forceinline__ float4 ldh4(const __half* __restrict__ p) {
    uint2 v = __ldg((const uint2*)p);
    __half2 h0 = *(__half2*)&v.x;
    __half2 h1 = *(__half2*)&v.y;
    float2 f0 = __half22float2(h0);
    float2 f1 = __half22float2(h1);
    return make_float4(f0.x, f0.y, f1.x, f1.y);
}

__device__ __forceinline__ void agg_body(
    const __half* __restrict__ h, int gw, int lane, int head,
    float4& acc, float& wsum)
{
    int beg = __ldg(&g_rowptr[gw]);
    int end = __ldg(&g_rowptr[gw + 1]);
    float adh = __ldg(((const float*)(g_AD + gw)) + head);

    int j = beg;
    for (; j + 4 <= end; j += 4) {
        int s0 = __ldg(&g_csrc[j]);
        int s1 = __ldg(&g_csrc[j + 1]);
        int s2 = __ldg(&g_csrc[j + 2]);
        int s3 = __ldg(&g_csrc[j + 3]);
        float a0 = __ldg(((const float*)(g_AS + s0)) + head);
        float a1 = __ldg(((const float*)(g_AS + s1)) + head);
        float a2 = __ldg(((const float*)(g_AS + s2)) + head);
        float a3 = __ldg(((const float*)(g_AS + s3)) + head);
        float4 h0 = ldh4(h + s0 * FDIM + lane * 4);
        float4 h1 = ldh4(h + s1 * FDIM + lane * 4);
        float4 h2 = ldh4(h + s2 * FDIM + lane * 4);
        float4 h3 = ldh4(h + s3 * FDIM + lane * 4);
        float w0 = __expf(leaky(a0 + adh));
        float w1 = __expf(leaky(a1 + adh));
        float w2 = __expf(leaky(a2 + adh));
        float w3 = __expf(leaky(a3 + adh));
        wsum += (w0 + w1) + (w2 + w3);
        acc.x = fmaf(h3.x, w3, fmaf(h2.x, w2, fmaf(h1.x, w1, fmaf(h0.x, w0, acc.x))));
        acc.y = fmaf(h3.y, w3, fmaf(h2.y, w2, fmaf(h1.y, w1, fmaf(h0.y, w0, acc.y))));
        acc.z = fmaf(h3.z, w3, fmaf(h2.z, w2, fmaf(h1.z, w1, fmaf(h0.z, w0, acc.z))));
        acc.w = fmaf(h3.w, w3, fmaf(h2.w, w2, fmaf(h1.w, w1, fmaf(h0.w, w0, acc.w))));
    }
    for (; j < end; j++) {
        int s = __ldg(&g_csrc[j]);
        float a = __ldg(((const float*)(g_AS + s)) + head);
        float w = __expf(leaky(a + adh));
        float4 hv = ldh4(h + s * FDIM + lane * 4);
        wsum += w;
        acc.x = fmaf(hv.x, w, acc.x);
        acc.y = fmaf(hv.y, w, acc.y);
        acc.z = fmaf(hv.z, w, acc.z);
        acc.w = fmaf(hv.w, w, acc.w);
    }
}

__global__ __launch_bounds__(256) void agg_fused_kernel(
    const __half* __restrict__ h, const float* __restrict__ bias,
    float* __restrict__ feat)
{
    int gw = (blockIdx.x * blockDim.x + threadIdx.x) >> 5;
    if (gw >= NN) return;
    int lane = threadIdx.x & 31;
    int head = lane >> 3;

    float4 acc = make_float4(0.f, 0.f, 0.f, 0.f);
    float wsum = 0.f;
    agg_body(h, gw, lane, head, acc, wsum);

    float inv = __fdividef(1.f, wsum + 1e-16f);
    float4 b = *(const float4*)(bias + lane * 4);
    float4 o;
    o.x = fmaxf(fmaf(acc.x, inv, b.x), 0.f);
    o.y = fmaxf(fmaf(acc.y, inv, b.y), 0.f);
    o.z = fmaxf(fmaf(acc.z, inv, b.z), 0.f);
    o.w = fmaxf(fmaf(acc.w, inv, b.w), 0.f);
    *(float4*)(feat + gw * FDIM + lane * 4) = o;
}

__global__ __launch_bounds__(256) void agg_final_kernel(
    const __half* __restrict__ h, const float* __restrict__ bias,
    float* __restrict__ out)
{
    int gw = (blockIdx.x * blockDim.x + threadIdx.x) >> 5;
    if (gw >= NN) return;
    int lane = threadIdx.x & 31;
    int head = lane >> 3;

    float4 acc = make_float4(0.f, 0.f, 0.f, 0.f);
    float wsum = 0.f;
    agg_body(h, gw, lane, head, acc, wsum);

    float inv = __fdividef(1.f, wsum + 1e-16f);
    float4 b = *(const float4*)(bias + lane * 4);
    float4 o;
    o.x = fmaxf(fmaf(acc.x, inv, b.x), 0.f);
    o.y = fmaxf(fmaf(acc.y, inv, b.y), 0.f);
    o.z = fmaxf(fmaf(acc.z, inv, b.z), 0.f);
    o.w = fmaxf(fmaf(acc.w, inv, b.w), 0.f);

    float4 w = *(const float4*)(g_weff + lane * 4);
    float p = o.x * w.x + o.y * w.y + o.z * w.z + o.w * w.w;
    #pragma unroll
    for (int of = 16; of >= 1; of >>= 1)
        p += __shfl_xor_sync(0xffffffffu, p, of);
    if (lane == 0) {
        float z = p + g_beff;
        out[gw] = __fdividef(1.f, 1.f + __expf(-z));
    }
}

// ---------------- classifier folding: w_eff = Wc1 @ Wc2 ------------------
__global__ void weff_kernel(const float* __restrict__ Wc1,
                            const float* __restrict__ bc1,
                            const float* __restrict__ Wc2,
                            const float* __restrict__ bc2)
{
    int t = threadIdx.x;
    if (t < 128) {
        float s = 0.f;
        #pragma unroll
        for (int j = 0; j < 32; j++) s += Wc1[t * 32 + j] * Wc2[j];
        g_weff[t] = s;
    }
    if (t == 0) {
        float b = bc2[0];
        for (int j = 0; j < 32; j++) b += bc1[j] * Wc2[j];
        g_beff = b;
    }
}

// ---------------- host launcher ----------------
extern "C" void kernel_launch(void* const* d_in, const int* in_sizes, int n_in,
                              void* d_out, int out_size)
{
    const float* x    = (const float*)d_in[0];
    const int*   ei   = (const int*)  d_in[1];
    const int*   esrc = ei;
    const int*   edst = ei + NE;
    const float* W1   = (const float*)d_in[2];
    const float* as1  = (const float*)d_in[3];
    const float* ad1  = (const float*)d_in[4];
    const float* b1   = (const float*)d_in[5];
    const float* W2   = (const float*)d_in[6];
    const float* as2  = (const float*)d_in[7];
    const float* ad2  = (const float*)d_in[8];
    const float* b2   = (const float*)d_in[9];
    const float* Wc1  = (const float*)d_in[10];
    const float* bc1  = (const float*)d_in[11];
    const float* Wc2  = (const float*)d_in[12];
    const float* bc2  = (const float*)d_in[13];
    float* out = (float*)d_out;

    __half* h16;  float* feat;
    cudaGetSymbolAddress((void**)&h16,  g_h16);
    cudaGetSymbolAddress((void**)&feat, g_feat);

    static cudaStream_t s2 = nullptr;
    static cudaEvent_t evFork = nullptr, evJoin = nullptr;
    if (!s2) {
        cudaStreamCreateWithFlags(&s2, cudaStreamNonBlocking);
        cudaEventCreateWithFlags(&evFork, cudaEventDisableTiming);
        cudaEventCreateWithFlags(&evJoin, cudaEventDisableTiming);
    }

    const size_t SMEM = (size_t)(64 * FDIM + FDIM * FDIM) * sizeof(float); // 96 KB
    cudaFuncSetAttribute(gemm_fused_kernel,
                         cudaFuncAttributeMaxDynamicSharedMemorySize, (int)SMEM);

    const int warpGrid = (NN * 32 + 255) / 256;
    const int gemmGrid = (NN + 63) / 64;
    const int e4Grid   = (NE / 4 + 255) / 256;
    const int e8Grid   = (NE / 8 + 255) / 256;
    const int nGrid    = (NN + 255) / 256;

    // Fork: CSR build + classifier fold concurrent with GEMM1
    cudaEventRecord(evFork, 0);
    cudaStreamWaitEvent(s2, evFork, 0);

    init_cnt_kernel<<<nGrid, 256, 0, s2>>>();
    count4_kernel<<<e4Grid, 256, 0, s2>>>(edst);
    scan1_kernel<<<NSCAN, SCANB, 0, s2>>>();
    scan2_kernel<<<1, 64, 0, s2>>>();
    scan3_kernel<<<nGrid, 256, 0, s2>>>();
    scatter8_kernel<<<e8Grid, 256, 0, s2>>>(esrc, edst);
    scatter_self_kernel<<<nGrid, 256, 0, s2>>>();
    weff_kernel<<<1, 128, 0, s2>>>(Wc1, bc1, Wc2, bc2);
    cudaEventRecord(evJoin, s2);

    // Layer 1: GEMM + alphas fused
    gemm_fused_kernel<<<gemmGrid, 256, SMEM>>>(x, W1, as1, ad1, h16, NN);

    cudaStreamWaitEvent(0, evJoin, 0);
    agg_fused_kernel<<<warpGrid, 256>>>(h16, b1, feat);

    // Layer 2
    gemm_fused_kernel<<<gemmGrid, 256, SMEM>>>(feat, W2, as2, ad2, h16, NN);
    agg_final_kernel<<<warpGrid, 256>>>(h16, b2, out);
}